// round 9
// baseline (speedup 1.0000x reference)
#include <cuda_runtime.h>

// Reference semantics reduce to (softmax over a size-1 axis == 1; W is dead code):
//   out[i, 0:512]    = 2*X[i]                              for i < 64
//   out[i, 0:512]    = X[i] + sum_{r=i-64..i-1} X[r]       for i >= 64
//   out[i, 512:1024] = X[i]
//
// Single fused kernel. Block = (chunk k of 64 output rows, group g of 8 f4 cols).
// k>=1: load 128 rows [64(k-1), 64k+64); rows 64..127 are ALSO the output rows,
// so stash them in smem (xbuf) during the load phase — the emit phase then does
// zero global loads. Exclusive prefix P[m] in smem; W[t] = P[t+64] - P[t].

#define NROWS 4096
#define DCOLS 512
#define LENS  64
#define D4    (DCOLS / 4)    // 128 f4 per input row
#define OD4   (2 * D4)       // 256 f4 per output row
#define CPB   8              // f4 columns per block
#define NG    (D4 / CPB)     // 16 column groups
#define NCH   (NROWS / LENS) // 64 chunks
#define SEG   8              // rows per load segment
#define NSEG  16             // 128 rows / 8

static __device__ __forceinline__ float4 f4add(float4 a, float4 b) {
    return make_float4(a.x + b.x, a.y + b.y, a.z + b.z, a.w + b.w);
}
static __device__ __forceinline__ float4 f4sub(float4 a, float4 b) {
    return make_float4(a.x - b.x, a.y - b.y, a.z - b.z, a.w - b.w);
}

__global__ __launch_bounds__(128, 8) void fused_window_kernel(
    const float4* __restrict__ X4, float4* __restrict__ O4)
{
    const int b   = blockIdx.x;
    const int k   = b >> 4;          // chunk 0..63
    const int g   = b & 15;          // column group 0..15
    const int tid = threadIdx.x;
    const int c   = tid & 7;         // column within group
    const int col = g * CPB + c;     // global f4 column

    if (k == 0) {
        // rows 0..63: left = 2X, right = X. 16 row-teams x 4 rows.
        const int u = tid >> 3;
        #pragma unroll
        for (int r = 0; r < 4; ++r) {
            const int i = u * 4 + r;
            float4 x = X4[(size_t)i * D4 + col];
            O4[(size_t)i * OD4 + col]      = f4add(x, x);
            O4[(size_t)i * OD4 + D4 + col] = x;
        }
        return;
    }

    __shared__ float4 P[129 * CPB];      // exclusive prefix over 128 loaded rows
    __shared__ float4 tot[NSEG * CPB];   // per-segment totals
    __shared__ float4 xbuf[LENS * CPB];  // raw x for output rows (loaded rows 64..127)

    // ---- Load phase: 8 independent LDG.128; stash output rows; local prefix ----
    const int s    = tid >> 3;           // segment 0..15
    const int base = (k - 1) * LENS;     // first loaded global row
    const float4* px = X4 + (size_t)(base + s * SEG) * D4 + col;

    float4 v[SEG];
    #pragma unroll
    for (int j = 0; j < SEG; ++j) v[j] = px[(size_t)j * D4];

    if (s >= 8) {                        // these are the output rows: stash raw x
        const int t0 = (s - 8) * SEG;
        #pragma unroll
        for (int j = 0; j < SEG; ++j)
            xbuf[(t0 + j) * CPB + c] = v[j];
    }

    #pragma unroll
    for (int j = 1; j < SEG; ++j) v[j] = f4add(v[j], v[j - 1]);

    tot[s * CPB + c] = v[SEG - 1];
    __syncthreads();

    // off = sum of segment totals below s (unrolled, predicated -> no serial loop)
    float4 off = make_float4(0.f, 0.f, 0.f, 0.f);
    #pragma unroll
    for (int j = 0; j < NSEG - 1; ++j) {
        float4 t = tot[j * CPB + c];
        if (s > j) off = f4add(off, t);
    }

    // Exclusive prefix: P[m] = sum of loaded rows [0, m)
    if (s == 0) P[c] = off;              // off == 0 here -> P[0] = 0
    #pragma unroll
    for (int j = 0; j < SEG; ++j)
        P[(s * SEG + j + 1) * CPB + c] = f4add(v[j], off);
    __syncthreads();

    // ---- Emit phase: pure smem reads + stores, no global loads ----
    const int u = tid >> 3;              // row team 0..15
    #pragma unroll
    for (int r = 0; r < 4; ++r) {
        const int t = u * 4 + r;         // 0..63
        const int i = k * LENS + t;      // global output row
        float4 w = f4sub(P[(t + 64) * CPB + c], P[t * CPB + c]);
        float4 x = xbuf[t * CPB + c];
        O4[(size_t)i * OD4 + col]      = f4add(x, w);
        O4[(size_t)i * OD4 + D4 + col] = x;
    }
}

extern "C" void kernel_launch(void* const* d_in, const int* in_sizes, int n_in,
                              void* d_out, int out_size)
{
    const float4* X4 = (const float4*)d_in[0];   // X: (4096, 512) f32
    float4* O4 = (float4*)d_out;                 // out: (4096, 1024) f32

    fused_window_kernel<<<NCH * NG, 128>>>(X4, O4);   // 1024 blocks, 1 launch
}

// round 10
// speedup vs baseline: 1.2149x; 1.2149x over previous
#include <cuda_runtime.h>

// Reference semantics reduce to (softmax over a size-1 axis == 1; W is dead code):
//   out[i, 0:512]    = 2*X[i]                              for i < 64
//   out[i, 0:512]    = X[i] + sum_{r=i-64..i-1} X[r]       for i >= 64
//   out[i, 512:1024] = X[i]
//
// Warp-autonomous design: ZERO smem, ZERO barriers.
// Warp = (chunk k of 64 output rows, 2 f4 columns).
// Lane l: segment s = l>>1 (16 segments x 8 rows = 128 loaded rows), col parity cc = l&1.
// Exclusive prefix over segment totals via 4-step stride-2 shfl_up.
// For upper lanes (s>=8, loaded rows 64..127 == the output rows):
//   H[row m] = acc_s(incl through j) - acc_{s-8}(excl of j), the latter via one shfl
//   from lane l-16 of the SAME warp. Right half = raw v[j] (kept in registers).

#define NROWS 4096
#define DCOLS 512
#define LENS  64
#define D4    (DCOLS / 4)   // 128 f4 per input row
#define OD4   (2 * D4)      // 256 f4 per output row
#define NCH   (NROWS / LENS) // 64 chunks

static __device__ __forceinline__ float4 f4add(float4 a, float4 b) {
    return make_float4(a.x + b.x, a.y + b.y, a.z + b.z, a.w + b.w);
}
static __device__ __forceinline__ float4 f4sub(float4 a, float4 b) {
    return make_float4(a.x - b.x, a.y - b.y, a.z - b.z, a.w - b.w);
}
static __device__ __forceinline__ float4 shfl_idx4(float4 v, int src) {
    float4 r;
    r.x = __shfl_sync(0xffffffffu, v.x, src);
    r.y = __shfl_sync(0xffffffffu, v.y, src);
    r.z = __shfl_sync(0xffffffffu, v.z, src);
    r.w = __shfl_sync(0xffffffffu, v.w, src);
    return r;
}
static __device__ __forceinline__ float4 shfl_up4(float4 v, int d) {
    float4 r;
    r.x = __shfl_up_sync(0xffffffffu, v.x, d);
    r.y = __shfl_up_sync(0xffffffffu, v.y, d);
    r.z = __shfl_up_sync(0xffffffffu, v.z, d);
    r.w = __shfl_up_sync(0xffffffffu, v.w, d);
    return r;
}

__global__ __launch_bounds__(128, 8) void warp_window_kernel(
    const float4* __restrict__ X4, float4* __restrict__ O4)
{
    const int wid  = blockIdx.x * 4 + (threadIdx.x >> 5);  // global warp id
    const int lane = threadIdx.x & 31;
    const int k    = wid >> 6;        // chunk 0..63 (16 consecutive blocks share a chunk)
    const int cp   = wid & 63;        // column pair 0..63
    const int cc   = lane & 1;
    const int s    = lane >> 1;       // segment 0..15
    const int col  = cp * 2 + cc;     // global f4 column

    if (k == 0) {
        // rows 0..63: left = 2X, right = X. Lane handles rows s*4..s*4+3.
        #pragma unroll
        for (int j = 0; j < 4; ++j) {
            const int i = s * 4 + j;
            float4 x = X4[(size_t)i * D4 + col];
            O4[(size_t)i * OD4 + col]      = f4add(x, x);
            O4[(size_t)i * OD4 + D4 + col] = x;
        }
        return;
    }

    // Load 8 raw rows: global rows base + s*8 + j, base = (k-1)*64.
    const int base = (k - 1) * LENS;
    const float4* px = X4 + (size_t)(base + s * 8) * D4 + col;
    float4 v[8];
    #pragma unroll
    for (int j = 0; j < 8; ++j) v[j] = px[(size_t)j * D4];

    // Segment total.
    float4 ls = v[0];
    #pragma unroll
    for (int j = 1; j < 8; ++j) ls = f4add(ls, v[j]);

    // Inclusive scan over segments (same-parity lanes, stride 2): d = 2,4,8,16.
    float4 inc = ls;
    #pragma unroll
    for (int d = 2; d < 32; d <<= 1) {
        float4 t = shfl_up4(inc, d);
        if (lane >= d) inc = f4add(inc, t);
    }
    // Exclusive prefix at segment start (exact 0 for s == 0).
    float4 acc = f4sub(inc, ls);

    // Emit: upper lanes (s >= 8) own output rows i = base + s*8 + j.
    //   B_j = acc of lane (l-16) BEFORE adding its v[j]  ==  P[m-64]
    //   H   = (acc after adding v[j]) - B_j;  right half = raw v[j].
    const int srcl = (lane >= 16) ? (lane - 16) : lane;
    #pragma unroll
    for (int j = 0; j < 8; ++j) {
        float4 B = shfl_idx4(acc, srcl);   // all lanes participate
        acc = f4add(acc, v[j]);
        if (lane >= 16) {
            const size_t i = (size_t)(base + s * 8 + j);   // output row
            O4[i * OD4 + col]      = f4sub(acc, B);
            O4[i * OD4 + D4 + col] = v[j];
        }
    }
}

extern "C" void kernel_launch(void* const* d_in, const int* in_sizes, int n_in,
                              void* d_out, int out_size)
{
    const float4* X4 = (const float4*)d_in[0];   // X: (4096, 512) f32
    float4* O4 = (float4*)d_out;                 // out: (4096, 1024) f32

    // 64 chunks x 64 column-pairs = 4096 warps = 1024 blocks of 128 threads.
    warp_window_kernel<<<NCH * 16, 128>>>(X4, O4);
}

// round 11
// speedup vs baseline: 1.5018x; 1.2362x over previous
#include <cuda_runtime.h>

// Reference semantics reduce to (softmax over a size-1 axis == 1; W is dead code):
//   out[i, 0:512]    = 2*X[i]                              for i < 64
//   out[i, 0:512]    = X[i] + sum_{r=i-64..i-1} X[r]       for i >= 64
//   out[i, 512:1024] = X[i]
//
// Single fused kernel, block = (chunk k of 64 output rows, group of 8 f4 cols).
// 16 segments x 8 rows = loaded rows [64(k-1), 64k+64).
// Upper segments (s>=8) OWN the output rows they loaded:
//   - right-half copy stores issue immediately from registers (pre-barrier)
//   - left half: H = v[j] + (acc - Plow[m-64]), acc = running exclusive prefix
//     kept in registers; Plow (only 64 entries) written by lower segments.

#define NROWS 4096
#define DCOLS 512
#define LENS  64
#define D4    (DCOLS / 4)    // 128 f4 per input row
#define OD4   (2 * D4)       // 256 f4 per output row
#define CPB   8              // f4 columns per block
#define NG    (D4 / CPB)     // 16 column groups
#define NCH   (NROWS / LENS) // 64 chunks
#define SEG   8
#define NSEG  16

static __device__ __forceinline__ float4 f4add(float4 a, float4 b) {
    return make_float4(a.x + b.x, a.y + b.y, a.z + b.z, a.w + b.w);
}
static __device__ __forceinline__ float4 f4sub(float4 a, float4 b) {
    return make_float4(a.x - b.x, a.y - b.y, a.z - b.z, a.w - b.w);
}

__global__ __launch_bounds__(128, 8) void fused_window_kernel(
    const float4* __restrict__ X4, float4* __restrict__ O4)
{
    const int b   = blockIdx.x;
    const int k   = b >> 4;          // chunk 0..63
    const int g   = b & 15;          // column group 0..15
    const int tid = threadIdx.x;
    const int c   = tid & 7;         // column within group
    const int col = g * CPB + c;     // global f4 column
    const int s   = tid >> 3;        // segment 0..15

    if (k == 0) {
        // rows 0..63: left = 2X, right = X. Segment s handles rows s*4..s*4+3.
        #pragma unroll
        for (int r = 0; r < 4; ++r) {
            const int i = s * 4 + r;
            float4 x = X4[(size_t)i * D4 + col];
            O4[(size_t)i * OD4 + col]      = f4add(x, x);
            O4[(size_t)i * OD4 + D4 + col] = x;
        }
        return;
    }

    __shared__ float4 tot[NSEG * CPB];   // per-segment totals (2 KB)
    __shared__ float4 Plow[LENS * CPB];  // exclusive prefix P[0..63] (4 KB)

    // ---- Load phase: 8 independent LDG.128 per thread ----
    const int base = (k - 1) * LENS;            // first loaded global row
    const float4* px = X4 + (size_t)(base + s * SEG) * D4 + col;
    float4 v[SEG];
    #pragma unroll
    for (int j = 0; j < SEG; ++j) v[j] = px[(size_t)j * D4];

    // Upper segments: right-half copy from registers, BEFORE any barrier.
    if (s >= 8) {
        float4* po = O4 + (size_t)(base + s * SEG) * OD4 + D4 + col;
        #pragma unroll
        for (int j = 0; j < SEG; ++j)
            po[(size_t)j * OD4] = v[j];
    }

    // Segment total (tree) -> smem.
    float4 s01 = f4add(v[0], v[1]);
    float4 s23 = f4add(v[2], v[3]);
    float4 s45 = f4add(v[4], v[5]);
    float4 s67 = f4add(v[6], v[7]);
    tot[s * CPB + c] = f4add(f4add(s01, s23), f4add(s45, s67));
    __syncthreads();

    // off = sum of segment totals below s (unrolled, predicated).
    float4 off = make_float4(0.f, 0.f, 0.f, 0.f);
    #pragma unroll
    for (int j = 0; j < NSEG - 1; ++j) {
        float4 t = tot[j * CPB + c];
        if (s > j) off = f4add(off, t);
    }

    if (s < 8) {
        // Lower segments: publish exclusive prefixes P[s*8+j] = off + sum v[0..j-1].
        float4 acc = off;
        float4* pp = Plow + (s * SEG) * CPB + c;
        #pragma unroll
        for (int j = 0; j < SEG; ++j) {
            pp[j * CPB] = acc;
            acc = f4add(acc, v[j]);
        }
        __syncthreads();          // all threads reach the barrier
    } else {
        __syncthreads();
        // Upper segments: emit left half from registers + one LDS per row.
        //   m = s*8 + j (loaded index of output row), P[m] = acc (before adding v[j])
        //   W = P[m] - Plow[m-64];  H = v[j] + W
        float4 acc = off;
        const float4* pl = Plow + ((s - 8) * SEG) * CPB + c;
        float4* po = O4 + (size_t)(base + s * SEG) * OD4 + col;
        #pragma unroll
        for (int j = 0; j < SEG; ++j) {
            float4 w = f4sub(acc, pl[j * CPB]);
            po[(size_t)j * OD4] = f4add(v[j], w);
            acc = f4add(acc, v[j]);
        }
    }
}

extern "C" void kernel_launch(void* const* d_in, const int* in_sizes, int n_in,
                              void* d_out, int out_size)
{
    const float4* X4 = (const float4*)d_in[0];   // X: (4096, 512) f32
    float4* O4 = (float4*)d_out;                 // out: (4096, 1024) f32

    fused_window_kernel<<<NCH * NG, 128>>>(X4, O4);   // 1024 blocks, 1 launch
}